// round 2
// baseline (speedup 1.0000x reference)
#include <cuda_runtime.h>
#include <math.h>

#define Bv 4
#define Cv 64
#define Ov 64
#define Hv 128
#define Wv 128
#define HWv (Hv*Wv)
#define K2 9
#define CO 27

// ---------------- scratch (no allocations allowed) ----------------
__device__ float g_offx[Bv*K2*HWv];
__device__ float g_offy[Bv*K2*HWv];
__device__ float g_mask[Bv*K2*HWv];
__device__ float g_wk[K2*Cv*Ov];   // [k][c][o]

// ---------------- kernel 0: repack w_def [o][c][k] -> [k][c][o] ----------------
__global__ void repack_w_kernel(const float* __restrict__ w_def) {
    int i = blockIdx.x * blockDim.x + threadIdx.x;   // 0 .. K2*Cv*Ov-1
    if (i >= K2 * Cv * Ov) return;
    int o = i % Ov;
    int c = (i / Ov) % Cv;
    int k = i / (Ov * Cv);
    g_wk[i] = w_def[(o * Cv + c) * K2 + k];
}

// ---------------- kernel 1: offset conv (feat -> offx/offy/mask) ----------------
// grid (H, B), 128 threads (one per w). smem: feat tile [3][64][130] + transposed weights [576][28]
#define SF_ELEMS (3*64*130)
#define SWT_ELEMS (576*28)
#define SMEM1_BYTES ((SF_ELEMS + SWT_ELEMS) * 4)

extern __shared__ float smem1[];

__global__ __launch_bounds__(128) void off_conv_kernel(
    const float* __restrict__ feat,
    const float* __restrict__ w_off,
    const float* __restrict__ b_off)
{
    const int h = blockIdx.x;
    const int b = blockIdx.y;
    const int t = threadIdx.x;   // 0..127 == w

    float* sf  = smem1;               // [ky][c][col] stride 130
    float* swt = smem1 + SF_ELEMS;    // [j=c*9+ky*3+kx][co] stride 28 (pad)

    // transpose-load weights: swt[j][co] = w_off[co][j]
    for (int i = t; i < 576 * CO; i += 128) {
        int j  = i / CO;
        int co = i % CO;
        swt[j * 28 + co] = w_off[co * 576 + j];
    }
    // load 3 feat rows (zero padded)
    for (int i = t; i < SF_ELEMS; i += 128) {
        int col = i % 130;
        int c   = (i / 130) % 64;
        int r   = i / (130 * 64);
        int hh = h + r - 1;
        int ww = col - 1;
        float v = 0.f;
        if (hh >= 0 && hh < Hv && ww >= 0 && ww < Wv)
            v = feat[((b * Cv + c) * Hv + hh) * Wv + ww];
        sf[i] = v;
    }
    __syncthreads();

    float acc[CO];
    #pragma unroll
    for (int co = 0; co < CO; co++) acc[co] = b_off[co];

    for (int c = 0; c < Cv; c++) {
        #pragma unroll
        for (int ky = 0; ky < 3; ky++) {
            #pragma unroll
            for (int kx = 0; kx < 3; kx++) {
                float f = sf[(ky * 64 + c) * 130 + t + kx];
                const float4* wr = (const float4*)&swt[(c * 9 + ky * 3 + kx) * 28];
                #pragma unroll
                for (int q = 0; q < 6; q++) {
                    float4 wv = wr[q];
                    acc[q*4+0] += f * wv.x;
                    acc[q*4+1] += f * wv.y;
                    acc[q*4+2] += f * wv.z;
                    acc[q*4+3] += f * wv.w;
                }
                float4 wv = wr[6];        // only .x .y .z valid (pad at 27)
                acc[24] += f * wv.x;
                acc[25] += f * wv.y;
                acc[26] += f * wv.z;
            }
        }
    }

    const int pix = h * Wv + t;
    #pragma unroll
    for (int k = 0; k < K2; k++) {
        int gi = (b * K2 + k) * HWv + pix;
        g_offx[gi] = acc[k];
        g_offy[gi] = acc[9 + k];
        float m = acc[18 + k];
        g_mask[gi] = 1.f / (1.f + __expf(-m));
    }
}

// ---------------- kernel 2: fused deform-sample + GEMM + bias + relu ----------------
// grid (H, B), 256 threads. One block computes out[b][:][h][:] (64 x 128).
struct Smem2 {
    float v[Cv][Wv];      // sampled tile for current tap  (32 KB)
    float wk[Cv][Ov];     // w_def slice for current tap   (16 KB)
    float offx[K2][Wv];
    float offy[K2][Wv];
    float mask[K2][Wv];   // 3 * 4.5 KB
};

__global__ __launch_bounds__(256) void deform_main_kernel(
    const float* __restrict__ x,
    const float* __restrict__ b_def,
    float* __restrict__ out)
{
    extern __shared__ char smem_raw[];
    Smem2& s = *reinterpret_cast<Smem2*>(smem_raw);

    const int h = blockIdx.x;
    const int b = blockIdx.y;
    const int t = threadIdx.x;

    // load offset/mask rows for all 9 taps
    for (int i = t; i < K2 * Wv; i += 256) {
        int k  = i / Wv;
        int px = i % Wv;
        int gi = (b * K2 + k) * HWv + h * Wv + px;
        s.offx[k][px] = g_offx[gi];
        s.offy[k][px] = g_offy[gi];
        s.mask[k][px] = g_mask[gi];
    }

    // GEMM micro-tile mapping: warp = 8 consecutive o's, lane covers 4 px
    const int oi  = t >> 5;          // 0..7
    const int pi  = t & 31;          // 0..31
    const int o0  = oi * 8;
    const int px0 = pi * 4;

    float acc[8][4];
    #pragma unroll
    for (int i = 0; i < 8; i++) {
        float bv = b_def[o0 + i];
        #pragma unroll
        for (int j = 0; j < 4; j++) acc[i][j] = bv;
    }

    // sampling mapping: thread handles one pixel, 32 channels
    const int spx = t & 127;
    const int c0  = (t >> 7) * 32;   // 0 or 32
    const float* xb = x + (size_t)(b * Cv + c0) * HWv;

    __syncthreads();   // offsets ready; nothing has touched v/wk yet

    for (int k = 0; k < K2; k++) {
        // cooperative load of this tap's weight slice [c][o]
        {
            const float4* gw = (const float4*)&g_wk[k * Cv * Ov];
            float4* sw4 = (float4*)&s.wk[0][0];
            #pragma unroll
            for (int i = 0; i < 4; i++)
                sw4[t + i * 256] = gw[t + i * 256];
        }

        // bilinear sample 64 x 128 tile (mask & validity folded into weights)
        {
            const int dy = k / 3 - 1;
            const int dx = k % 3 - 1;
            float ys = (float)(h + dy) + s.offy[k][spx];
            float xs = (float)(spx + dx) + s.offx[k][spx];
            float m  = s.mask[k][spx];
            float y0f = floorf(ys), x0f = floorf(xs);
            float wy1 = ys - y0f,  wx1 = xs - x0f;
            float wy0 = 1.f - wy1, wx0 = 1.f - wx1;
            int y0 = (int)y0f, x0i = (int)x0f;
            int y1 = y0 + 1,   x1  = x0i + 1;
            float vy0 = (y0 >= 0 && y0 < Hv) ? 1.f : 0.f;
            float vy1 = (y1 >= 0 && y1 < Hv) ? 1.f : 0.f;
            float vx0 = (x0i >= 0 && x0i < Wv) ? 1.f : 0.f;
            float vx1 = (x1 >= 0 && x1 < Wv) ? 1.f : 0.f;
            int y0c = min(max(y0, 0), Hv - 1);
            int y1c = min(max(y1, 0), Hv - 1);
            int x0c = min(max(x0i, 0), Wv - 1);
            int x1c = min(max(x1, 0), Wv - 1);
            float w00 = wy0 * wx0 * vy0 * vx0 * m;
            float w01 = wy0 * wx1 * vy0 * vx1 * m;
            float w10 = wy1 * wx0 * vy1 * vx0 * m;
            float w11 = wy1 * wx1 * vy1 * vx1 * m;
            int i00 = y0c * Wv + x0c;
            int i01 = y0c * Wv + x1c;
            int i10 = y1c * Wv + x0c;
            int i11 = y1c * Wv + x1c;

            #pragma unroll 4
            for (int c = 0; c < 32; c++) {
                const float* xc = xb + (size_t)c * HWv;
                float val = w00 * __ldg(xc + i00)
                          + w01 * __ldg(xc + i01)
                          + w10 * __ldg(xc + i10)
                          + w11 * __ldg(xc + i11);
                s.v[c0 + c][spx] = val;
            }
        }
        __syncthreads();   // v & wk ready

        // register-blocked GEMM: acc[8][4] += wk[c][o0..o0+7] x v[c][px0..px0+3]
        #pragma unroll 8
        for (int c = 0; c < Cv; c++) {
            float4 wa = *(const float4*)&s.wk[c][o0];
            float4 wb = *(const float4*)&s.wk[c][o0 + 4];
            float4 vv = *(const float4*)&s.v[c][px0];
            float wreg[8] = {wa.x, wa.y, wa.z, wa.w, wb.x, wb.y, wb.z, wb.w};
            float vreg[4] = {vv.x, vv.y, vv.z, vv.w};
            #pragma unroll
            for (int i = 0; i < 8; i++)
                #pragma unroll
                for (int j = 0; j < 4; j++)
                    acc[i][j] += wreg[i] * vreg[j];
        }
        __syncthreads();   // done reading v/wk before next tap overwrites
    }

    // epilogue: ReLU + store (float4, coalesced)
    #pragma unroll
    for (int i = 0; i < 8; i++) {
        float4 r;
        r.x = fmaxf(acc[i][0], 0.f);
        r.y = fmaxf(acc[i][1], 0.f);
        r.z = fmaxf(acc[i][2], 0.f);
        r.w = fmaxf(acc[i][3], 0.f);
        *(float4*)&out[((b * Ov + (o0 + i)) * Hv + h) * Wv + px0] = r;
    }
}

// ---------------- launch ----------------
extern "C" void kernel_launch(void* const* d_in, const int* in_sizes, int n_in,
                              void* d_out, int out_size)
{
    const float* x     = (const float*)d_in[0];
    const float* feat  = (const float*)d_in[1];
    const float* w_off = (const float*)d_in[2];
    const float* b_off = (const float*)d_in[3];
    const float* w_def = (const float*)d_in[4];
    const float* b_def = (const float*)d_in[5];
    float* out = (float*)d_out;

    cudaFuncSetAttribute(off_conv_kernel,
                         cudaFuncAttributeMaxDynamicSharedMemorySize, SMEM1_BYTES);
    cudaFuncSetAttribute(deform_main_kernel,
                         cudaFuncAttributeMaxDynamicSharedMemorySize, (int)sizeof(Smem2));

    repack_w_kernel<<<(K2 * Cv * Ov + 255) / 256, 256>>>(w_def);
    off_conv_kernel<<<dim3(Hv, Bv), 128, SMEM1_BYTES>>>(feat, w_off, b_off);
    deform_main_kernel<<<dim3(Hv, Bv), 256, sizeof(Smem2)>>>(x, b_def, out);
}

// round 3
// speedup vs baseline: 1.4922x; 1.4922x over previous
#include <cuda_runtime.h>
#include <math.h>

#define Bv 4
#define Cv 64
#define Ov 64
#define Hv 128
#define Wv 128
#define HWv (Hv*Wv)
#define K2 9
#define CO 27

typedef unsigned long long u64;

__device__ __forceinline__ u64 pk2(float a, float b) {
    u64 r; asm("mov.b64 %0, {%1,%2};" : "=l"(r) : "f"(a), "f"(b)); return r;
}
__device__ __forceinline__ void fma2(u64& d, u64 a, u64 b) {
    asm("fma.rn.f32x2 %0, %1, %2, %0;" : "+l"(d) : "l"(a), "l"(b));
}
__device__ __forceinline__ float2 up2(u64 v) {
    float lo, hi; asm("mov.b64 {%0,%1}, %2;" : "=f"(lo), "=f"(hi) : "l"(v));
    return make_float2(lo, hi);
}

// ---------------- scratch ----------------
__device__ float g_offx[Bv*K2*HWv];
__device__ float g_offy[Bv*K2*HWv];
__device__ float g_mask[Bv*K2*HWv];
__device__ float g_wk[K2*Cv*Ov];   // [k][c][o]

// ---------------- kernel 0: repack w_def [o][c][k] -> [k][c][o] ----------------
__global__ void repack_w_kernel(const float* __restrict__ w_def) {
    int i = blockIdx.x * blockDim.x + threadIdx.x;
    if (i >= K2 * Cv * Ov) return;
    int o = i % Ov;
    int c = (i / Ov) % Cv;
    int k = i / (Ov * Cv);
    g_wk[i] = w_def[(o * Cv + c) * K2 + k];
}

// ---------------- kernel 1: offset conv, channel-chunked, f32x2 ----------------
#define CCH 16
#define NCHUNK (Cv/CCH)

__global__ __launch_bounds__(128) void off_conv_kernel(
    const float* __restrict__ feat,
    const float* __restrict__ w_off,
    const float* __restrict__ b_off)
{
    __shared__ float sf[3][CCH][130];        // feat chunk, zero-padded cols
    __shared__ float swc[CCH*9][28];         // weights chunk, transposed, col 27 = 0

    const int h = blockIdx.x;
    const int b = blockIdx.y;
    const int t = threadIdx.x;   // 0..127 == w

    u64 acc[14];
    #pragma unroll
    for (int q = 0; q < 14; q++) {
        float lo = b_off[2*q];
        float hi = (2*q + 1 < CO) ? b_off[2*q + 1] : 0.f;
        acc[q] = pk2(lo, hi);
    }

    for (int chunk = 0; chunk < NCHUNK; chunk++) {
        const int c0 = chunk * CCH;
        __syncthreads();   // previous chunk's compute done before overwrite

        // weights: swc[cc*9+tap][co] = w_off[co][c0+cc][tap]
        for (int i = t; i < CCH*9*28; i += 128) {
            int j  = i / 28;
            int co = i % 28;
            swc[j][co] = (co < CO) ? w_off[co * 576 + c0 * 9 + j] : 0.f;
        }
        // feat chunk [r][cc][col], zero padded
        for (int i = t; i < 3*CCH*130; i += 128) {
            int col = i % 130;
            int cc  = (i / 130) % CCH;
            int r   = i / (130 * CCH);
            int hh = h + r - 1;
            int ww = col - 1;
            float v = 0.f;
            if (hh >= 0 && hh < Hv && ww >= 0 && ww < Wv)
                v = feat[((b * Cv + c0 + cc) * Hv + hh) * Wv + ww];
            (&sf[0][0][0])[i] = v;
        }
        __syncthreads();

        #pragma unroll 2
        for (int cc = 0; cc < CCH; cc++) {
            #pragma unroll
            for (int ky = 0; ky < 3; ky++) {
                #pragma unroll
                for (int kx = 0; kx < 3; kx++) {
                    float f = sf[ky][cc][t + kx];
                    u64 ff = pk2(f, f);
                    const float4* wr = (const float4*)&swc[cc*9 + ky*3 + kx][0];
                    #pragma unroll
                    for (int q = 0; q < 7; q++) {
                        float4 wv = wr[q];
                        fma2(acc[2*q],     ff, pk2(wv.x, wv.y));
                        fma2(acc[2*q + 1], ff, pk2(wv.z, wv.w));
                    }
                }
            }
        }
    }

    float o[28];
    #pragma unroll
    for (int q = 0; q < 14; q++) {
        float2 p = up2(acc[q]);
        o[2*q] = p.x; o[2*q+1] = p.y;
    }

    const int pix = h * Wv + t;
    #pragma unroll
    for (int k = 0; k < K2; k++) {
        int gi = (b * K2 + k) * HWv + pix;
        g_offx[gi] = o[k];
        g_offy[gi] = o[9 + k];
        float m = o[18 + k];
        g_mask[gi] = 1.f / (1.f + __expf(-m));
    }
}

// ---------------- kernel 2: fused sample + f32x2 GEMM + bias + relu ----------------
// grid (H, B), 128 threads. Block computes out[b][:][h][:] (64 x 128).
// Thread micro-tile: 8 o x 8 px.
struct Smem2 {
    float v[Cv][Wv];          // 32 KB sampled tile (current tap)
    u64   wk2[Cv][Ov];        // 32 KB duplicated (w,w) pairs (current tap)
    float offx[K2][Wv];
    float offy[K2][Wv];
    float mask[K2][Wv];
};

__global__ __launch_bounds__(128, 2) void deform_main_kernel(
    const float* __restrict__ x,
    const float* __restrict__ b_def,
    float* __restrict__ out)
{
    extern __shared__ char smem_raw[];
    Smem2& s = *reinterpret_cast<Smem2*>(smem_raw);

    const int h = blockIdx.x;
    const int b = blockIdx.y;
    const int t = threadIdx.x;

    // load offset/mask rows for all 9 taps
    for (int i = t; i < K2 * Wv; i += 128) {
        int k  = i >> 7;
        int px = i & 127;
        int gi = (b * K2 + k) * HWv + h * Wv + px;
        s.offx[k][px] = g_offx[gi];
        s.offy[k][px] = g_offy[gi];
        s.mask[k][px] = g_mask[gi];
    }

    const int og  = t >> 4;          // 0..7
    const int o0  = og * 8;
    const int px0 = (t & 15) * 8;

    u64 acc[8][4];
    #pragma unroll
    for (int i = 0; i < 8; i++) {
        float bv = b_def[o0 + i];
        u64 p = pk2(bv, bv);
        #pragma unroll
        for (int j = 0; j < 4; j++) acc[i][j] = p;
    }

    const float* xb = x + (size_t)b * Cv * HWv;

    __syncthreads();   // offsets ready

    for (int k = 0; k < K2; k++) {
        // cooperative load of tap weight slice as duplicated pairs
        {
            const float4* gw = (const float4*)&g_wk[k * Cv * Ov];
            #pragma unroll
            for (int j = 0; j < 8; j++) {
                float4 w = gw[t + j * 128];
                int e = (t + j * 128) * 4;
                int c = e >> 6;
                int o = e & 63;
                ulonglong2* dst = (ulonglong2*)&s.wk2[c][o];
                dst[0] = make_ulonglong2(pk2(w.x, w.x), pk2(w.y, w.y));
                dst[1] = make_ulonglong2(pk2(w.z, w.z), pk2(w.w, w.w));
            }
        }

        // bilinear sample: thread handles pixel t, all 64 channels
        {
            const int dy = k / 3 - 1;
            const int dx = k % 3 - 1;
            float ys = (float)(h + dy) + s.offy[k][t];
            float xs = (float)(t + dx) + s.offx[k][t];
            float m  = s.mask[k][t];
            float y0f = floorf(ys), x0f = floorf(xs);
            float wy1 = ys - y0f,  wx1 = xs - x0f;
            float wy0 = 1.f - wy1, wx0 = 1.f - wx1;
            int y0 = (int)y0f, x0i = (int)x0f;
            int y1 = y0 + 1,   x1  = x0i + 1;
            float vy0 = (y0 >= 0 && y0 < Hv) ? 1.f : 0.f;
            float vy1 = (y1 >= 0 && y1 < Hv) ? 1.f : 0.f;
            float vx0 = (x0i >= 0 && x0i < Wv) ? 1.f : 0.f;
            float vx1 = (x1 >= 0 && x1 < Wv) ? 1.f : 0.f;
            int y0c = min(max(y0, 0), Hv - 1);
            int y1c = min(max(y1, 0), Hv - 1);
            int x0c = min(max(x0i, 0), Wv - 1);
            int x1c = min(max(x1, 0), Wv - 1);
            float w00 = wy0 * wx0 * vy0 * vx0 * m;
            float w01 = wy0 * wx1 * vy0 * vx1 * m;
            float w10 = wy1 * wx0 * vy1 * vx0 * m;
            float w11 = wy1 * wx1 * vy1 * vx1 * m;
            int i00 = y0c * Wv + x0c;
            int i01 = y0c * Wv + x1c;
            int i10 = y1c * Wv + x0c;
            int i11 = y1c * Wv + x1c;

            #pragma unroll 4
            for (int c = 0; c < Cv; c++) {
                const float* xc = xb + (size_t)c * HWv;
                float val = w00 * __ldg(xc + i00)
                          + w01 * __ldg(xc + i01)
                          + w10 * __ldg(xc + i10)
                          + w11 * __ldg(xc + i11);
                s.v[c][t] = val;
            }
        }
        __syncthreads();   // v & wk2 ready

        // f32x2 register-blocked GEMM: acc[8o][8px]
        #pragma unroll 4
        for (int c = 0; c < Cv; c++) {
            const u64* wr = &s.wk2[c][o0];
            const float4* vr = (const float4*)&s.v[c][px0];
            float4 va = vr[0], vb = vr[1];
            u64 v0 = pk2(va.x, va.y), v1 = pk2(va.z, va.w);
            u64 v2 = pk2(vb.x, vb.y), v3 = pk2(vb.z, vb.w);
            u64 w[8];
            #pragma unroll
            for (int i = 0; i < 8; i++) w[i] = wr[i];
            #pragma unroll
            for (int i = 0; i < 8; i++) {
                fma2(acc[i][0], w[i], v0);
                fma2(acc[i][1], w[i], v1);
                fma2(acc[i][2], w[i], v2);
                fma2(acc[i][3], w[i], v3);
            }
        }
        __syncthreads();   // done reading before next tap overwrites
    }

    // epilogue: ReLU + store
    #pragma unroll
    for (int i = 0; i < 8; i++) {
        float2 p0 = up2(acc[i][0]);
        float2 p1 = up2(acc[i][1]);
        float2 p2 = up2(acc[i][2]);
        float2 p3 = up2(acc[i][3]);
        float4 r0, r1;
        r0.x = fmaxf(p0.x, 0.f); r0.y = fmaxf(p0.y, 0.f);
        r0.z = fmaxf(p1.x, 0.f); r0.w = fmaxf(p1.y, 0.f);
        r1.x = fmaxf(p2.x, 0.f); r1.y = fmaxf(p2.y, 0.f);
        r1.z = fmaxf(p3.x, 0.f); r1.w = fmaxf(p3.y, 0.f);
        float* op = &out[((b * Ov + (o0 + i)) * Hv + h) * Wv + px0];
        *(float4*)op = r0;
        *(float4*)(op + 4) = r1;
    }
}

// ---------------- launch ----------------
extern "C" void kernel_launch(void* const* d_in, const int* in_sizes, int n_in,
                              void* d_out, int out_size)
{
    const float* x     = (const float*)d_in[0];
    const float* feat  = (const float*)d_in[1];
    const float* w_off = (const float*)d_in[2];
    const float* b_off = (const float*)d_in[3];
    const float* w_def = (const float*)d_in[4];
    const float* b_def = (const float*)d_in[5];
    float* out = (float*)d_out;

    cudaFuncSetAttribute(deform_main_kernel,
                         cudaFuncAttributeMaxDynamicSharedMemorySize, (int)sizeof(Smem2));

    repack_w_kernel<<<(K2 * Cv * Ov + 255) / 256, 256>>>(w_def);
    off_conv_kernel<<<dim3(Hv, Bv), 128>>>(feat, w_off, b_off);
    deform_main_kernel<<<dim3(Hv, Bv), 128, sizeof(Smem2)>>>(x, b_def, out);
}

// round 4
// speedup vs baseline: 1.8097x; 1.2128x over previous
#include <cuda_runtime.h>
#include <math.h>

#define Bv 4
#define Cv 64
#define Ov 64
#define Hv 128
#define Wv 128
#define HWv (Hv*Wv)
#define K2 9
#define CO 27

typedef unsigned long long u64;

__device__ __forceinline__ u64 pk2(float a, float b) {
    u64 r; asm("mov.b64 %0, {%1,%2};" : "=l"(r) : "f"(a), "f"(b)); return r;
}
__device__ __forceinline__ void fma2(u64& d, u64 a, u64 b) {
    asm("fma.rn.f32x2 %0, %1, %2, %0;" : "+l"(d) : "l"(a), "l"(b));
}
__device__ __forceinline__ float2 up2(u64 v) {
    float lo, hi; asm("mov.b64 {%0,%1}, %2;" : "=f"(lo), "=f"(hi) : "l"(v));
    return make_float2(lo, hi);
}
__device__ __forceinline__ void bar_sync256(int id) {
    asm volatile("bar.sync %0, 256;" :: "r"(id) : "memory");
}
__device__ __forceinline__ void bar_arrive256(int id) {
    asm volatile("bar.arrive %0, 256;" :: "r"(id) : "memory");
}

// barrier ids
#define BFULL0 1
#define BFULL1 2
#define BEMPTY0 3
#define BEMPTY1 4

// ---------------- scratch ----------------
__device__ float g_offx[Bv*K2*HWv];
__device__ float g_offy[Bv*K2*HWv];
__device__ float g_mask[Bv*K2*HWv];
__device__ float g_wk[K2*Cv*Ov];   // [k][c][o]

// ---------------- kernel 0: repack w_def [o][c][k] -> [k][c][o] ----------------
__global__ void repack_w_kernel(const float* __restrict__ w_def) {
    int i = blockIdx.x * blockDim.x + threadIdx.x;
    if (i >= K2 * Cv * Ov) return;
    int o = i % Ov;
    int c = (i / Ov) % Cv;
    int k = i / (Ov * Cv);
    g_wk[i] = w_def[(o * Cv + c) * K2 + k];
}

// ---------------- kernel 1: offset conv, channel-chunked, packed weights ----------------
#define CCH 16
#define NCHUNK (Cv/CCH)

__global__ __launch_bounds__(128) void off_conv_kernel(
    const float* __restrict__ feat,
    const float* __restrict__ w_off,
    const float* __restrict__ b_off)
{
    __shared__ float sf[3][CCH][130];      // feat chunk, zero-padded cols
    __shared__ u64   swc2[CCH*9][14];      // weight pairs (co 2q, 2q+1), co27 = 0

    const int h = blockIdx.x;
    const int b = blockIdx.y;
    const int t = threadIdx.x;   // 0..127 == w

    u64 acc[14];
    #pragma unroll
    for (int q = 0; q < 14; q++) {
        float lo = b_off[2*q];
        float hi = (2*q + 1 < CO) ? b_off[2*q + 1] : 0.f;
        acc[q] = pk2(lo, hi);
    }

    for (int chunk = 0; chunk < NCHUNK; chunk++) {
        const int c0 = chunk * CCH;
        __syncthreads();   // previous chunk's compute done before overwrite

        // weight pairs: swc2[j][q] = (w_off[2q][c0..][j], w_off[2q+1][...])
        for (int i = t; i < CCH*9*14; i += 128) {
            int j = i / 14;
            int q = i % 14;
            float lo = w_off[(2*q) * 576 + c0 * 9 + j];
            float hi = (2*q + 1 < CO) ? w_off[(2*q + 1) * 576 + c0 * 9 + j] : 0.f;
            swc2[j][q] = pk2(lo, hi);
        }
        // feat chunk [r][cc][col], zero padded
        for (int i = t; i < 3*CCH*130; i += 128) {
            int col = i % 130;
            int cc  = (i / 130) % CCH;
            int r   = i / (130 * CCH);
            int hh = h + r - 1;
            int ww = col - 1;
            float v = 0.f;
            if (hh >= 0 && hh < Hv && ww >= 0 && ww < Wv)
                v = feat[((b * Cv + c0 + cc) * Hv + hh) * Wv + ww];
            (&sf[0][0][0])[i] = v;
        }
        __syncthreads();

        #pragma unroll 2
        for (int cc = 0; cc < CCH; cc++) {
            #pragma unroll
            for (int ky = 0; ky < 3; ky++) {
                #pragma unroll
                for (int kx = 0; kx < 3; kx++) {
                    float f = sf[ky][cc][t + kx];
                    u64 ff = pk2(f, f);
                    const u64* wr = &swc2[cc*9 + ky*3 + kx][0];
                    #pragma unroll
                    for (int q = 0; q < 14; q++)
                        fma2(acc[q], ff, wr[q]);
                }
            }
        }
    }

    float o[28];
    #pragma unroll
    for (int q = 0; q < 14; q++) {
        float2 p = up2(acc[q]);
        o[2*q] = p.x; o[2*q+1] = p.y;
    }

    const int pix = h * Wv + t;
    #pragma unroll
    for (int k = 0; k < K2; k++) {
        int gi = (b * K2 + k) * HWv + pix;
        g_offx[gi] = o[k];
        g_offy[gi] = o[9 + k];
        float m = o[18 + k];
        g_mask[gi] = 1.f / (1.f + __expf(-m));
    }
}

// ---------------- kernel 2: warp-specialized sample + f32x2 GEMM ----------------
// grid (H, B), 256 threads. warps 0-3 produce (sample + weights), warps 4-7 consume (GEMM).
struct Smem2 {
    float v[2][Cv][Wv];       // 64 KB double-buffered sampled tiles
    float wk[2][Cv][Ov];      // 32 KB double-buffered weight slices
    float offx[K2][Wv];
    float offy[K2][Wv];
    float mask[K2][Wv];       // 13.5 KB
};

__global__ __launch_bounds__(256, 2) void deform_main_kernel(
    const float* __restrict__ x,
    const float* __restrict__ b_def,
    float* __restrict__ out)
{
    extern __shared__ char smem_raw[];
    Smem2& s = *reinterpret_cast<Smem2*>(smem_raw);

    const int h = blockIdx.x;
    const int b = blockIdx.y;
    const int t = threadIdx.x;

    // load offset/mask rows for all 9 taps (all 256 threads)
    for (int i = t; i < K2 * Wv; i += 256) {
        int k  = i >> 7;
        int px = i & 127;
        int gi = (b * K2 + k) * HWv + h * Wv + px;
        s.offx[k][px] = g_offx[gi];
        s.offy[k][px] = g_offy[gi];
        s.mask[k][px] = g_mask[gi];
    }
    __syncthreads();

    if (t < 128) {
        // ================= PRODUCER: sample + weight staging =================
        const int px = t;
        const float* xb = x + (size_t)b * Cv * HWv;

        for (int k = 0; k < K2; k++) {
            const int p = k & 1;
            if (k >= 2) bar_sync256(BEMPTY0 + p);   // consumer done with this parity

            // stage weights [c][o] for this tap
            {
                const float4* gw = (const float4*)&g_wk[k * Cv * Ov];
                float4* sw = (float4*)&s.wk[p][0][0];
                #pragma unroll
                for (int j = 0; j < 8; j++)
                    sw[t + j * 128] = gw[t + j * 128];
            }

            // bilinear sample: this thread's pixel, all 64 channels
            {
                const int dy = k / 3 - 1;
                const int dx = k % 3 - 1;
                float ys = (float)(h + dy) + s.offy[k][px];
                float xs = (float)(px + dx) + s.offx[k][px];
                float m  = s.mask[k][px];
                float y0f = floorf(ys), x0f = floorf(xs);
                float wy1 = ys - y0f,  wx1 = xs - x0f;
                float wy0 = 1.f - wy1, wx0 = 1.f - wx1;
                int y0 = (int)y0f, x0i = (int)x0f;
                int y1 = y0 + 1,   x1  = x0i + 1;
                float vy0 = (y0 >= 0 && y0 < Hv) ? 1.f : 0.f;
                float vy1 = (y1 >= 0 && y1 < Hv) ? 1.f : 0.f;
                float vx0 = (x0i >= 0 && x0i < Wv) ? 1.f : 0.f;
                float vx1 = (x1 >= 0 && x1 < Wv) ? 1.f : 0.f;
                int y0c = min(max(y0, 0), Hv - 1);
                int y1c = min(max(y1, 0), Hv - 1);
                int x0c = min(max(x0i, 0), Wv - 1);
                int x1c = min(max(x1, 0), Wv - 1);
                float w00 = wy0 * wx0 * vy0 * vx0 * m;
                float w01 = wy0 * wx1 * vy0 * vx1 * m;
                float w10 = wy1 * wx0 * vy1 * vx0 * m;
                float w11 = wy1 * wx1 * vy1 * vx1 * m;
                int i00 = y0c * Wv + x0c;
                int i01 = y0c * Wv + x1c;
                int i10 = y1c * Wv + x0c;
                int i11 = y1c * Wv + x1c;

                #pragma unroll 4
                for (int c = 0; c < Cv; c++) {
                    const float* xc = xb + (size_t)c * HWv;
                    float val = w00 * __ldg(xc + i00)
                              + w01 * __ldg(xc + i01)
                              + w10 * __ldg(xc + i10)
                              + w11 * __ldg(xc + i11);
                    s.v[p][c][px] = val;
                }
            }

            __threadfence_block();          // make STS visible before signaling
            bar_arrive256(BFULL0 + p);      // buffer p full
        }
    } else {
        // ================= CONSUMER: f32x2 GEMM =================
        const int tc  = t - 128;
        const int o0  = (tc >> 4) * 8;
        const int px0 = (tc & 15) * 8;

        u64 acc[8][4];
        #pragma unroll
        for (int i = 0; i < 8; i++) {
            float bv = b_def[o0 + i];
            u64 pr = pk2(bv, bv);
            #pragma unroll
            for (int j = 0; j < 4; j++) acc[i][j] = pr;
        }

        for (int k = 0; k < K2; k++) {
            const int p = k & 1;
            bar_sync256(BFULL0 + p);        // wait buffer full

            #pragma unroll 4
            for (int c = 0; c < Cv; c++) {
                float4 wa = *(const float4*)&s.wk[p][c][o0];
                float4 wb = *(const float4*)&s.wk[p][c][o0 + 4];
                u64 w[8];
                w[0] = pk2(wa.x, wa.x); w[1] = pk2(wa.y, wa.y);
                w[2] = pk2(wa.z, wa.z); w[3] = pk2(wa.w, wa.w);
                w[4] = pk2(wb.x, wb.x); w[5] = pk2(wb.y, wb.y);
                w[6] = pk2(wb.z, wb.z); w[7] = pk2(wb.w, wb.w);
                // adjacent pixels are already packed pairs in smem
                ulonglong2 va = *(const ulonglong2*)&s.v[p][c][px0];
                ulonglong2 vb = *(const ulonglong2*)&s.v[p][c][px0 + 4];
                #pragma unroll
                for (int i = 0; i < 8; i++) {
                    fma2(acc[i][0], w[i], va.x);
                    fma2(acc[i][1], w[i], va.y);
                    fma2(acc[i][2], w[i], vb.x);
                    fma2(acc[i][3], w[i], vb.y);
                }
            }

            bar_arrive256(BEMPTY0 + p);     // buffer p consumed
        }

        // epilogue: ReLU + store
        #pragma unroll
        for (int i = 0; i < 8; i++) {
            float2 p0 = up2(acc[i][0]);
            float2 p1 = up2(acc[i][1]);
            float2 p2 = up2(acc[i][2]);
            float2 p3 = up2(acc[i][3]);
            float4 r0, r1;
            r0.x = fmaxf(p0.x, 0.f); r0.y = fmaxf(p0.y, 0.f);
            r0.z = fmaxf(p1.x, 0.f); r0.w = fmaxf(p1.y, 0.f);
            r1.x = fmaxf(p2.x, 0.f); r1.y = fmaxf(p2.y, 0.f);
            r1.z = fmaxf(p3.x, 0.f); r1.w = fmaxf(p3.y, 0.f);
            float* op = &out[((b * Ov + (o0 + i)) * Hv + h) * Wv + px0];
            *(float4*)op = r0;
            *(float4*)(op + 4) = r1;
        }
    }
}

// ---------------- launch ----------------
extern "C" void kernel_launch(void* const* d_in, const int* in_sizes, int n_in,
                              void* d_out, int out_size)
{
    const float* x     = (const float*)d_in[0];
    const float* feat  = (const float*)d_in[1];
    const float* w_off = (const float*)d_in[2];
    const float* b_off = (const float*)d_in[3];
    const float* w_def = (const float*)d_in[4];
    const float* b_def = (const float*)d_in[5];
    float* out = (float*)d_out;

    cudaFuncSetAttribute(deform_main_kernel,
                         cudaFuncAttributeMaxDynamicSharedMemorySize, (int)sizeof(Smem2));

    repack_w_kernel<<<(K2 * Cv * Ov + 255) / 256, 256>>>(w_def);
    off_conv_kernel<<<dim3(Hv, Bv), 128>>>(feat, w_off, b_off);
    deform_main_kernel<<<dim3(Hv, Bv), 256, sizeof(Smem2)>>>(x, b_def, out);
}